// round 8
// baseline (speedup 1.0000x reference)
#include <cuda_runtime.h>
#include <stdint.h>

#define BATCH 2
#define CDIM  256
#define SPA   32768          // 32*32*32 spatial per batch
#define TOK   (BATCH*SPA)    // 65536 tokens
#define NE    1024

// output layout (floats)
#define ZQ_OFF   0
#define LOSS_OFF 16777216
#define IDX_OFF  16777217
#define SAMP_OFF 16842753
#define MCD_OFF  16844801
#define MCV_OFF  16844802

// ---------------- scratch (device globals; no allocation allowed) ----------------
__device__ float g_sume2[NE];
__device__ int   g_idx[TOK];
__device__ float g_loss_part[256];
__device__ __align__(16) float g_embT[CDIM * NE];
__device__ float g_md[NE];
__device__ float g_var[NE];

// ---------------- cp.async / f32x2 helpers ----------------
__device__ __forceinline__ void cpa16(uint32_t s, const void* g) {
    asm volatile("cp.async.cg.shared.global [%0], [%1], 16;" :: "r"(s), "l"(g));
}
__device__ __forceinline__ void cpa_commit() {
    asm volatile("cp.async.commit_group;");
}
// packed fp32x2 FMA: each 32-bit lane rounds exactly like scalar fma.rn.f32
__device__ __forceinline__ unsigned long long ffma2(unsigned long long a,
                                                    unsigned long long b,
                                                    unsigned long long c) {
    unsigned long long d;
    asm("fma.rn.f32x2 %0, %1, %2, %3;" : "=l"(d) : "l"(a), "l"(b), "l"(c));
    return d;
}
__device__ __forceinline__ unsigned long long bcast2(float x) {
    unsigned long long p;
    asm("mov.b64 %0, {%1, %1};" : "=l"(p) : "f"(x));
    return p;
}
__device__ __forceinline__ float lane_lo(unsigned long long v) {
    return __uint_as_float((unsigned)(v & 0xffffffffull));
}
__device__ __forceinline__ float lane_hi(unsigned long long v) {
    return __uint_as_float((unsigned)(v >> 32));
}

// ---------------- K1: per-code squared norms ----------------
__global__ void k_sume2(const float* __restrict__ emb) {
    int row  = blockIdx.x * 8 + threadIdx.y;   // block (32,8), grid 128
    int lane = threadIdx.x;
    const float* e = emb + (size_t)row * CDIM;
    float s = 0.f;
    #pragma unroll
    for (int k = lane; k < CDIM; k += 32) { float v = e[k]; s = fmaf(v, v, s); }
    #pragma unroll
    for (int o = 16; o; o >>= 1) s += __shfl_xor_sync(0xffffffffu, s, o);
    if (lane == 0) g_sume2[row] = s;
}

// ---------------- K_T: transpose emb -> embT[k][i] ----------------
__global__ void k_embT(const float* __restrict__ emb) {
    __shared__ float tile[32][33];
    int i0 = blockIdx.x * 32;   // code dim (1024/32 = 32 blocks x)
    int k0 = blockIdx.y * 32;   // k dim    (256/32 = 8 blocks y)
    int tx = threadIdx.x, ty = threadIdx.y;   // block (32,8)
    #pragma unroll
    for (int r = 0; r < 4; r++)
        tile[ty + 8 * r][tx] = emb[(size_t)(i0 + ty + 8 * r) * CDIM + k0 + tx];
    __syncthreads();
    #pragma unroll
    for (int r = 0; r < 4; r++)
        g_embT[(size_t)(k0 + ty + 8 * r) * NE + i0 + tx] = tile[tx][ty + 8 * r];
}

// ---------------- K3: distance + argmin ----------------
// 64-token x 1024-code per block; 4 code tiles of 256; k chunks of 16.
// cp.async 2-stage double buffer; 128 threads; 8 tokens x 16 codes per thread.
// fma.rn.f32x2 packed over ADJACENT CODE PAIRS: each fp32 lane is an
// independent dot product accumulated in ascending-k order with fma.rn
// rounding -> bitwise identical distances/argmin vs the scalar version.
__launch_bounds__(128, 2)
__global__ void k_dist(const float* __restrict__ z) {
    __shared__ __align__(16) float as_[2][16][64];    // 8 KB
    __shared__ __align__(16) float es_[2][16][256];   // 32 KB
    __shared__ unsigned long long bkey[64];

    const int tid = threadIdx.x;
    const int tb  = blockIdx.x;            // 1024 blocks
    const int b   = tb >> 9;               // batch
    const int s0  = (tb & 511) << 6;       // 64-token tile start
    const float* zb = z + (size_t)b * CDIM * SPA + s0;

    const int tx = tid & 15;               // code sub (x16)
    const int ty = tid >> 4;               // token sub (x8)

    if (tid < 64) bkey[tid] = ~0ull;

    float    minv[8];
    unsigned mini[8];
    float    areg[8];                      // sum z^2 per token (scalar, ascending k)
    #pragma unroll
    for (int i = 0; i < 8; i++) { minv[i] = 3.4e38f; mini[i] = 0u; areg[i] = 0.f; }

    unsigned long long acc2[8][8];         // [token][code-pair]

    const uint32_t sa = (uint32_t)__cvta_generic_to_shared(&as_[0][0][0]);
    const uint32_t se = (uint32_t)__cvta_generic_to_shared(&es_[0][0][0]);

    // issue chunk c: nt=c>>4 (code tile of 256), kc=c&15 (k chunk), buffer c&1
    // A granules: 16 rows x 16 granules = 256 -> 2 per thread
    // B granules: 16 rows x 64 granules = 1024 -> 8 per thread
    #define ISSUE(c) do {                                                         \
        int nt_ = (c) >> 4, kc_ = (c) & 15, bf_ = (c) & 1;                        \
        const float* zsrc = zb + (size_t)(kc_ * 16) * SPA;                        \
        _Pragma("unroll")                                                         \
        for (int i = 0; i < 2; i++) {                                             \
            int idx = i * 128 + tid;                                              \
            int row = idx >> 4, cg = (idx & 15) << 2;                             \
            cpa16(sa + (uint32_t)((bf_*16*64) + row*64 + cg) * 4u,                \
                  zsrc + (size_t)row * SPA + cg);                                 \
        }                                                                         \
        const float* esrc = g_embT + (size_t)(kc_ * 16) * NE + nt_ * 256;         \
        _Pragma("unroll")                                                         \
        for (int i = 0; i < 8; i++) {                                             \
            int idx = i * 128 + tid;                                              \
            int row = idx >> 6, cg = (idx & 63) << 2;                             \
            cpa16(se + (uint32_t)((bf_*16*256) + row*256 + cg) * 4u,              \
                  esrc + (size_t)row * NE + cg);                                  \
        }                                                                         \
        cpa_commit();                                                             \
    } while (0)

    ISSUE(0);

    for (int c = 0; c < 64; c++) {
        const int bf = c & 1;

        // Barrier BEFORE issuing into buffer bf^1: all threads done reading it.
        __syncthreads();
        if (c < 63) {
            ISSUE(c + 1);
            asm volatile("cp.async.wait_group 1;");
        } else {
            asm volatile("cp.async.wait_group 0;");
        }
        __syncthreads();   // chunk c data visible block-wide

        if ((c & 15) == 0) {
            #pragma unroll
            for (int i = 0; i < 8; i++)
                #pragma unroll
                for (int j = 0; j < 8; j++) acc2[i][j] = 0ull;
        }

        const bool fnt = (c < 16);   // first code tile: also accumulate sum z^2

        #pragma unroll
        for (int k = 0; k < 16; k++) {
            float ar[8];
            *(float4*)(ar)     = *(const float4*)&as_[bf][k][ty * 8];
            *(float4*)(ar + 4) = *(const float4*)&as_[bf][k][ty * 8 + 4];
            // 16 codes as 8 adjacent pairs, straight from LDS.128
            ulonglong2 bv0 = *(const ulonglong2*)&es_[bf][k][tx * 16];
            ulonglong2 bv1 = *(const ulonglong2*)&es_[bf][k][tx * 16 + 4];
            ulonglong2 bv2 = *(const ulonglong2*)&es_[bf][k][tx * 16 + 8];
            ulonglong2 bv3 = *(const ulonglong2*)&es_[bf][k][tx * 16 + 12];
            unsigned long long bp[8] = { bv0.x, bv0.y, bv1.x, bv1.y,
                                         bv2.x, bv2.y, bv3.x, bv3.y };
            if (fnt) {
                #pragma unroll
                for (int i = 0; i < 8; i++) areg[i] = fmaf(ar[i], ar[i], areg[i]);
            }
            #pragma unroll
            for (int i = 0; i < 8; i++) {
                unsigned long long ap = bcast2(ar[i]);
                #pragma unroll
                for (int j = 0; j < 8; j++)
                    acc2[i][j] = ffma2(ap, bp[j], acc2[i][j]);
            }
        }

        if ((c & 15) == 15) {
            const int nt = c >> 4;
            // epilogue: d = RN(a+b) - 2m, argmin ascending (lo lane = even code)
            #pragma unroll
            for (int j = 0; j < 8; j++) {
                int code0 = nt * 256 + tx * 16 + 2 * j;
                float b0 = g_sume2[code0];
                float b1 = g_sume2[code0 + 1];
                #pragma unroll
                for (int i = 0; i < 8; i++) {
                    float m0 = lane_lo(acc2[i][j]);
                    float m1 = lane_hi(acc2[i][j]);
                    float t0 = __fadd_rn(areg[i], b0);
                    float t1 = __fadd_rn(areg[i], b1);
                    float d0 = fmaf(-2.f, m0, t0);
                    float d1 = fmaf(-2.f, m1, t1);
                    if (d0 < minv[i]) { minv[i] = d0; mini[i] = (unsigned)code0; }
                    if (d1 < minv[i]) { minv[i] = d1; mini[i] = (unsigned)(code0 + 1); }
                }
            }
        }
    }
    #undef ISSUE

    __syncthreads();
    #pragma unroll
    for (int i = 0; i < 8; i++) {
        unsigned long long key = ((unsigned long long)__float_as_uint(minv[i]) << 32)
                               | (unsigned long long)mini[i];
        atomicMin(&bkey[ty * 8 + i], key);
    }
    __syncthreads();
    if (tid < 64)
        g_idx[b * SPA + s0 + tid] = (int)(bkey[tid] & 0xffffffffull);
}

// ---------------- K_init: zero sampled_idx region ----------------
__global__ void k_init(float* __restrict__ out) {
    int i = blockIdx.x * blockDim.x + threadIdx.x;
    if (i < 2048) out[SAMP_OFF + i] = 0.f;
}

// ---------------- K4: gather z_q, straight-through output, loss partials, idx/sampled ----------------
__global__ void k_gather(const float* __restrict__ z, const float* __restrict__ emb,
                         float* __restrict__ out) {
    int t = blockIdx.x * 256 + threadIdx.x;   // grid 256, block 256
    int b = t >> 15;
    int s = t & (SPA - 1);
    const float* zb = z   + (size_t)b * CDIM * SPA + s;
    float*       ob = out + (size_t)b * CDIM * SPA + s;   // ZQ_OFF == 0
    int idx = g_idx[t];
    const float* e = emb + (size_t)idx * CDIM;

    float lsum = 0.f;
    #pragma unroll 4
    for (int c = 0; c < CDIM; c += 4) {
        float4 ev = *(const float4*)(e + c);
        float zp0 = zb[(size_t)(c + 0) * SPA];
        float zp1 = zb[(size_t)(c + 1) * SPA];
        float zp2 = zb[(size_t)(c + 2) * SPA];
        float zp3 = zb[(size_t)(c + 3) * SPA];
        float y0 = __fsub_rn(ev.x, zp0);
        float y1 = __fsub_rn(ev.y, zp1);
        float y2 = __fsub_rn(ev.z, zp2);
        float y3 = __fsub_rn(ev.w, zp3);
        ob[(size_t)(c + 0) * SPA] = __fadd_rn(zp0, y0);  // zp + sg(zq-zp)
        ob[(size_t)(c + 1) * SPA] = __fadd_rn(zp1, y1);
        ob[(size_t)(c + 2) * SPA] = __fadd_rn(zp2, y2);
        ob[(size_t)(c + 3) * SPA] = __fadd_rn(zp3, y3);
        lsum = fmaf(y0, y0, lsum);
        lsum = fmaf(y1, y1, lsum);
        lsum = fmaf(y2, y2, lsum);
        lsum = fmaf(y3, y3, lsum);
    }

    out[IDX_OFF + t] = (float)idx;
    out[SAMP_OFF + idx] = 1.0f;          // races benign: all write 1.0

    __shared__ float red[256];
    red[threadIdx.x] = lsum;
    __syncthreads();
    #pragma unroll
    for (int o = 128; o; o >>= 1) {
        if (threadIdx.x < o) red[threadIdx.x] += red[threadIdx.x + o];
        __syncthreads();
    }
    if (threadIdx.x == 0) g_loss_part[blockIdx.x] = red[0];
}

// ---------------- K6: codebook self-distance stats (4 rows per block) ----------------
__launch_bounds__(256)
__global__ void k_cbstats(const float* __restrict__ emb) {
    __shared__ float ejs[4][256];
    __shared__ float sm1[256], sm2[256];
    __shared__ double ss1[256], ss2[256];

    int tid = threadIdx.x;
    int j0  = blockIdx.x * 4;     // grid 256

    #pragma unroll
    for (int jj = 0; jj < 4; jj++)
        ejs[jj][tid] = emb[(size_t)(j0 + jj) * CDIM + tid];
    __syncthreads();

    float acc[4][4];
    #pragma unroll
    for (int jj = 0; jj < 4; jj++)
        #pragma unroll
        for (int r = 0; r < 4; r++) acc[jj][r] = 0.f;

    for (int k = 0; k < CDIM; k++) {
        float v[4];
        #pragma unroll
        for (int r = 0; r < 4; r++) v[r] = g_embT[(size_t)k * NE + tid + 256 * r];
        #pragma unroll
        for (int jj = 0; jj < 4; jj++) {
            float e = ejs[jj][k];
            #pragma unroll
            for (int r = 0; r < 4; r++) acc[jj][r] = fmaf(e, v[r], acc[jj][r]);
        }
    }

    float m1[4], m2[4];
    double s1[4], s2[4];
    #pragma unroll
    for (int jj = 0; jj < 4; jj++) { m1[jj] = 3.4e38f; m2[jj] = 3.4e38f; s1[jj] = 0.0; s2[jj] = 0.0; }

    #pragma unroll
    for (int jj = 0; jj < 4; jj++) {
        float nj = g_sume2[j0 + jj];
        #pragma unroll
        for (int r = 0; r < 4; r++) {
            int i = tid + 256 * r;
            float cdv = fmaf(-2.f, acc[jj][r], __fadd_rn(nj, g_sume2[i]));
            if (cdv < m1[jj]) { m2[jj] = m1[jj]; m1[jj] = cdv; }
            else if (cdv < m2[jj]) m2[jj] = cdv;
            s1[jj] += (double)cdv;
            s2[jj] += (double)cdv * (double)cdv;
        }
    }

    for (int jj = 0; jj < 4; jj++) {
        sm1[tid] = m1[jj]; sm2[tid] = m2[jj]; ss1[tid] = s1[jj]; ss2[tid] = s2[jj];
        __syncthreads();
        for (int o = 128; o; o >>= 1) {
            if (tid < o) {
                float a1 = sm1[tid], a2 = sm2[tid];
                float b1 = sm1[tid + o], b2 = sm2[tid + o];
                float n1 = fminf(a1, b1);
                float n2 = fminf(fmaxf(a1, b1), fminf(a2, b2));
                sm1[tid] = n1; sm2[tid] = n2;
                ss1[tid] += ss1[tid + o];
                ss2[tid] += ss2[tid + o];
            }
            __syncthreads();
        }
        if (tid == 0) {
            g_md[j0 + jj] = sm2[0];   // second smallest (diag ~0 is the smallest)
            double var = (ss2[0] - ss1[0] * ss1[0] / 1024.0) / 1023.0;
            g_var[j0 + jj] = (float)var;
        }
        __syncthreads();
    }
}

// ---------------- K5: final scalars ----------------
__global__ void k_final(float* __restrict__ out) {
    __shared__ double red[256];
    int tid = threadIdx.x;

    // loss
    red[tid] = (double)g_loss_part[tid];
    __syncthreads();
    #pragma unroll
    for (int o = 128; o; o >>= 1) {
        if (tid < o) red[tid] += red[tid + o];
        __syncthreads();
    }
    if (tid == 0) {
        float m = (float)(red[0] / (double)((size_t)TOK * CDIM));
        out[LOSS_OFF] = __fadd_rn(__fmul_rn(0.2f, m), m);   // beta*mse + mse
    }
    __syncthreads();

    // mean codebook distance + variance
    double a = 0.0, v = 0.0;
    for (int i = tid; i < NE; i += 256) { a += (double)g_md[i]; v += (double)g_var[i]; }
    red[tid] = a; __syncthreads();
    #pragma unroll
    for (int o = 128; o; o >>= 1) { if (tid < o) red[tid] += red[tid + o]; __syncthreads(); }
    if (tid == 0) out[MCD_OFF] = (float)(red[0] / 1024.0);
    __syncthreads();
    red[tid] = v; __syncthreads();
    #pragma unroll
    for (int o = 128; o; o >>= 1) { if (tid < o) red[tid] += red[tid + o]; __syncthreads(); }
    if (tid == 0) out[MCV_OFF] = (float)(red[0] / 1024.0);
}

// ---------------- launch ----------------
extern "C" void kernel_launch(void* const* d_in, const int* in_sizes, int n_in,
                              void* d_out, int out_size) {
    const float* z   = (const float*)d_in[0];
    const float* emb = (const float*)d_in[1];
    float* out = (float*)d_out;

    k_sume2 <<<128, dim3(32, 8)>>>(emb);
    k_embT  <<<dim3(32, 8), dim3(32, 8)>>>(emb);
    k_dist  <<<1024, 128>>>(z);
    k_init  <<<8, 256>>>(out);
    k_gather<<<256, 256>>>(z, emb, out);
    k_cbstats<<<256, 256>>>(emb);
    k_final <<<1, 256>>>(out);
}

// round 13
// speedup vs baseline: 1.4747x; 1.4747x over previous
#include <cuda_runtime.h>
#include <stdint.h>

#define BATCH 2
#define CDIM  256
#define SPA   32768          // 32*32*32 spatial per batch
#define TOK   (BATCH*SPA)    // 65536 tokens
#define NE    1024

// output layout (floats)
#define ZQ_OFF   0
#define LOSS_OFF 16777216
#define IDX_OFF  16777217
#define SAMP_OFF 16842753
#define MCD_OFF  16844801
#define MCV_OFF  16844802

// ---------------- scratch (device globals; no allocation allowed) ----------------
__device__ float g_sume2[NE];
__device__ int   g_idx[TOK];
__device__ float g_loss_part[256];
__device__ __align__(16) float g_embT[CDIM * NE];
__device__ float g_md[NE];
__device__ float g_var[NE];

// ---------------- cp.async / f32x2 helpers ----------------
__device__ __forceinline__ void cpa16(uint32_t s, const void* g) {
    asm volatile("cp.async.cg.shared.global [%0], [%1], 16;" :: "r"(s), "l"(g));
}
__device__ __forceinline__ void cpa_commit() {
    asm volatile("cp.async.commit_group;");
}
// packed fp32x2 FMA: each 32-bit lane rounds exactly like scalar fma.rn.f32
__device__ __forceinline__ unsigned long long ffma2(unsigned long long a,
                                                    unsigned long long b,
                                                    unsigned long long c) {
    unsigned long long d;
    asm("fma.rn.f32x2 %0, %1, %2, %3;" : "=l"(d) : "l"(a), "l"(b), "l"(c));
    return d;
}
__device__ __forceinline__ unsigned long long bcast2(float x) {
    unsigned long long p;
    asm("mov.b64 %0, {%1, %1};" : "=l"(p) : "f"(x));
    return p;
}
__device__ __forceinline__ float lane_lo(unsigned long long v) {
    return __uint_as_float((unsigned)(v & 0xffffffffull));
}
__device__ __forceinline__ float lane_hi(unsigned long long v) {
    return __uint_as_float((unsigned)(v >> 32));
}
__device__ __forceinline__ unsigned long long u64min(unsigned long long a,
                                                     unsigned long long b) {
    return a < b ? a : b;
}

// ---------------- K1: per-code squared norms ----------------
__global__ void k_sume2(const float* __restrict__ emb) {
    int row  = blockIdx.x * 8 + threadIdx.y;   // block (32,8), grid 128
    int lane = threadIdx.x;
    const float* e = emb + (size_t)row * CDIM;
    float s = 0.f;
    #pragma unroll
    for (int k = lane; k < CDIM; k += 32) { float v = e[k]; s = fmaf(v, v, s); }
    #pragma unroll
    for (int o = 16; o; o >>= 1) s += __shfl_xor_sync(0xffffffffu, s, o);
    if (lane == 0) g_sume2[row] = s;
}

// ---------------- K_T: transpose emb -> embT[k][i] ----------------
__global__ void k_embT(const float* __restrict__ emb) {
    __shared__ float tile[32][33];
    int i0 = blockIdx.x * 32;   // code dim (1024/32 = 32 blocks x)
    int k0 = blockIdx.y * 32;   // k dim    (256/32 = 8 blocks y)
    int tx = threadIdx.x, ty = threadIdx.y;   // block (32,8)
    #pragma unroll
    for (int r = 0; r < 4; r++)
        tile[ty + 8 * r][tx] = emb[(size_t)(i0 + ty + 8 * r) * CDIM + k0 + tx];
    __syncthreads();
    #pragma unroll
    for (int r = 0; r < 4; r++)
        g_embT[(size_t)(k0 + ty + 8 * r) * NE + i0 + tx] = tile[tx][ty + 8 * r];
}

// ---------------- K3: distance + argmin ----------------
// 64-token x 1024-code per block; 8 code tiles of 128; k chunks of 16.
// 4-stage cp.async pipeline, prefetch distance 2, ONE barrier per chunk:
//   ISSUE(c+2) -> wait_group -> __syncthreads -> compute(c)
// WAR safe: stage (c+2)&3 was read in compute(c-2); all threads finished it
// before iter c-1's collective barrier. RAW safe: every thread waits its own
// group c before the barrier; barrier publishes all copies.
// 128 threads; 8 tokens x 8 codes per thread; fma.rn.f32x2 packed over the
// TOKEN axis: each fp32 lane is its own dot product, ascending-k, fma.rn
// rounding -> bitwise identical distances/argmin vs scalar reference match.
__launch_bounds__(128, 4)
__global__ void k_dist(const float* __restrict__ z) {
    __shared__ __align__(16) float as_[4][16][64];    // 16 KB
    __shared__ __align__(16) float es_[4][16][128];   // 32 KB  (total 48 KB exactly)

    const int tid = threadIdx.x;
    const int tb  = blockIdx.x;            // 1024 blocks
    const int b   = tb >> 9;               // batch
    const int s0  = (tb & 511) << 6;       // 64-token tile start
    const float* zb = z + (size_t)b * CDIM * SPA + s0;

    const int tx = tid & 15;               // code sub (x8)
    const int ty = tid >> 4;               // token sub (x8)

    float    minv[8];
    unsigned mini[8];
    #pragma unroll
    for (int i = 0; i < 8; i++) { minv[i] = 3.4e38f; mini[i] = 0u; }

    unsigned long long areg2[4];           // packed sum z^2 (token pairs)
    #pragma unroll
    for (int p = 0; p < 4; p++) areg2[p] = 0ull;

    unsigned long long acc2[4][8];         // [token-pair][code]

    const uint32_t sa = (uint32_t)__cvta_generic_to_shared(&as_[0][0][0]);
    const uint32_t se = (uint32_t)__cvta_generic_to_shared(&es_[0][0][0]);

    // load granule decomposition
    const int a_row = tid >> 4;            // 0..7 (+8 for 2nd granule)
    const int a_col = (tid & 15) << 2;     // float index 0..60
    const int e_row = tid >> 5;            // 0..3 (+4r)
    const int e_col = (tid & 31) << 2;     // float index 0..124

    // issue chunk c: nt=c>>4 (code tile), kc=c&15 (k chunk), stage c&3
    #define ISSUE(c) do {                                                        \
        int nt_ = (c) >> 4, kc_ = (c) & 15, bf_ = (c) & 3;                       \
        const float* zsrc = zb + (size_t)(kc_ * 16) * SPA;                       \
        cpa16(sa + (uint32_t)((bf_*16*64) + a_row*64 + a_col) * 4u,              \
              zsrc + (size_t)a_row * SPA + a_col);                               \
        cpa16(sa + (uint32_t)((bf_*16*64) + (a_row+8)*64 + a_col) * 4u,          \
              zsrc + (size_t)(a_row + 8) * SPA + a_col);                         \
        const float* esrc = g_embT + (size_t)(kc_ * 16) * NE + nt_ * 128;        \
        cpa16(se + (uint32_t)((bf_*16*128) + (e_row+0)*128 + e_col) * 4u,        \
              esrc + (size_t)(e_row + 0)  * NE + e_col);                         \
        cpa16(se + (uint32_t)((bf_*16*128) + (e_row+4)*128 + e_col) * 4u,        \
              esrc + (size_t)(e_row + 4)  * NE + e_col);                         \
        cpa16(se + (uint32_t)((bf_*16*128) + (e_row+8)*128 + e_col) * 4u,        \
              esrc + (size_t)(e_row + 8)  * NE + e_col);                         \
        cpa16(se + (uint32_t)((bf_*16*128) + (e_row+12)*128 + e_col) * 4u,       \
              esrc + (size_t)(e_row + 12) * NE + e_col);                         \
        cpa_commit();                                                            \
    } while (0)

    ISSUE(0);
    ISSUE(1);

    for (int c = 0; c < 128; c++) {
        const int bf = c & 3;

        if (c + 2 < 128) {
            ISSUE(c + 2);
            asm volatile("cp.async.wait_group 2;");
        } else if (c == 126) {
            asm volatile("cp.async.wait_group 1;");
        } else {
            asm volatile("cp.async.wait_group 0;");
        }
        __syncthreads();   // single barrier per chunk (see header comment)

        if ((c & 15) == 0) {
            #pragma unroll
            for (int p = 0; p < 4; p++)
                #pragma unroll
                for (int j = 0; j < 8; j++) acc2[p][j] = 0ull;
        }

        const bool fnt = (c < 16);   // first code tile: also accumulate sum z^2

        #pragma unroll
        for (int k = 0; k < 16; k++) {
            // token pairs as natural 8-byte lanes of the LDS.128 loads
            ulonglong2 av0 = *(const ulonglong2*)&as_[bf][k][ty * 8];
            ulonglong2 av1 = *(const ulonglong2*)&as_[bf][k][ty * 8 + 4];
            unsigned long long arp[4] = { av0.x, av0.y, av1.x, av1.y };
            float br[8];
            *(float4*)(br)     = *(const float4*)&es_[bf][k][tx * 8];
            *(float4*)(br + 4) = *(const float4*)&es_[bf][k][tx * 8 + 4];
            if (fnt) {
                #pragma unroll
                for (int p = 0; p < 4; p++) areg2[p] = ffma2(arp[p], arp[p], areg2[p]);
            }
            #pragma unroll
            for (int j = 0; j < 8; j++) {
                unsigned long long bp = bcast2(br[j]);
                #pragma unroll
                for (int p = 0; p < 4; p++)
                    acc2[p][j] = ffma2(arp[p], bp, acc2[p][j]);
            }
        }

        if ((c & 15) == 15) {
            const int nt = c >> 4;
            // epilogue: d = RN(a+b) - 2m, argmin with ascending-index tie-break
            float areg[8];
            #pragma unroll
            for (int p = 0; p < 4; p++) {
                areg[2 * p]     = lane_lo(areg2[p]);
                areg[2 * p + 1] = lane_hi(areg2[p]);
            }
            #pragma unroll
            for (int j = 0; j < 8; j++) {
                int code = nt * 128 + tx * 8 + j;
                float bb = g_sume2[code];
                #pragma unroll
                for (int p = 0; p < 4; p++) {
                    float m0 = lane_lo(acc2[p][j]);
                    float m1 = lane_hi(acc2[p][j]);
                    float t0 = __fadd_rn(areg[2 * p], bb);
                    float t1 = __fadd_rn(areg[2 * p + 1], bb);
                    float d0 = fmaf(-2.f, m0, t0);
                    float d1 = fmaf(-2.f, m1, t1);
                    if (d0 < minv[2 * p])     { minv[2 * p]     = d0; mini[2 * p]     = (unsigned)code; }
                    if (d1 < minv[2 * p + 1]) { minv[2 * p + 1] = d1; mini[2 * p + 1] = (unsigned)code; }
                }
            }
        }
    }
    #undef ISSUE

    // cross-thread argmin: 16 candidate threads per token row are 16 contiguous
    // lanes (lane = (ty&1)*16 + tx) -> butterfly u64-min over offsets 1,2,4,8.
    // key = (d_bits<<32)|code : min picks smallest d, ties to lowest code
    // (identical semantics to the previous packed atomicMin).
    #pragma unroll
    for (int i = 0; i < 8; i++) {
        unsigned long long key = ((unsigned long long)__float_as_uint(minv[i]) << 32)
                               | (unsigned long long)mini[i];
        #pragma unroll
        for (int o = 1; o < 16; o <<= 1)
            key = u64min(key, __shfl_xor_sync(0xffffffffu, key, o));
        if (tx == 0)
            g_idx[b * SPA + s0 + ty * 8 + i] = (int)(key & 0xffffffffull);
    }
}

// ---------------- K_init: zero sampled_idx region ----------------
__global__ void k_init(float* __restrict__ out) {
    int i = blockIdx.x * blockDim.x + threadIdx.x;
    if (i < 2048) out[SAMP_OFF + i] = 0.f;
}

// ---------------- K4: gather z_q, straight-through output, loss partials, idx/sampled ----------------
__global__ void k_gather(const float* __restrict__ z, const float* __restrict__ emb,
                         float* __restrict__ out) {
    int t = blockIdx.x * 256 + threadIdx.x;   // grid 256, block 256
    int b = t >> 15;
    int s = t & (SPA - 1);
    const float* zb = z   + (size_t)b * CDIM * SPA + s;
    float*       ob = out + (size_t)b * CDIM * SPA + s;   // ZQ_OFF == 0
    int idx = g_idx[t];
    const float* e = emb + (size_t)idx * CDIM;

    float lsum = 0.f;
    #pragma unroll 4
    for (int c = 0; c < CDIM; c += 4) {
        float4 ev = *(const float4*)(e + c);
        float zp0 = zb[(size_t)(c + 0) * SPA];
        float zp1 = zb[(size_t)(c + 1) * SPA];
        float zp2 = zb[(size_t)(c + 2) * SPA];
        float zp3 = zb[(size_t)(c + 3) * SPA];
        float y0 = __fsub_rn(ev.x, zp0);
        float y1 = __fsub_rn(ev.y, zp1);
        float y2 = __fsub_rn(ev.z, zp2);
        float y3 = __fsub_rn(ev.w, zp3);
        ob[(size_t)(c + 0) * SPA] = __fadd_rn(zp0, y0);  // zp + sg(zq-zp)
        ob[(size_t)(c + 1) * SPA] = __fadd_rn(zp1, y1);
        ob[(size_t)(c + 2) * SPA] = __fadd_rn(zp2, y2);
        ob[(size_t)(c + 3) * SPA] = __fadd_rn(zp3, y3);
        lsum = fmaf(y0, y0, lsum);
        lsum = fmaf(y1, y1, lsum);
        lsum = fmaf(y2, y2, lsum);
        lsum = fmaf(y3, y3, lsum);
    }

    out[IDX_OFF + t] = (float)idx;
    out[SAMP_OFF + idx] = 1.0f;          // races benign: all write 1.0

    __shared__ float red[256];
    red[threadIdx.x] = lsum;
    __syncthreads();
    #pragma unroll
    for (int o = 128; o; o >>= 1) {
        if (threadIdx.x < o) red[threadIdx.x] += red[threadIdx.x + o];
        __syncthreads();
    }
    if (threadIdx.x == 0) g_loss_part[blockIdx.x] = red[0];
}

// ---------------- K6: codebook self-distance stats (4 rows per block) ----------------
__launch_bounds__(256)
__global__ void k_cbstats(const float* __restrict__ emb) {
    __shared__ float ejs[4][256];
    __shared__ float sm1[256], sm2[256];
    __shared__ double ss1[256], ss2[256];

    int tid = threadIdx.x;
    int j0  = blockIdx.x * 4;     // grid 256

    #pragma unroll
    for (int jj = 0; jj < 4; jj++)
        ejs[jj][tid] = emb[(size_t)(j0 + jj) * CDIM + tid];
    __syncthreads();

    float acc[4][4];
    #pragma unroll
    for (int jj = 0; jj < 4; jj++)
        #pragma unroll
        for (int r = 0; r < 4; r++) acc[jj][r] = 0.f;

    for (int k = 0; k < CDIM; k++) {
        float v[4];
        #pragma unroll
        for (int r = 0; r < 4; r++) v[r] = g_embT[(size_t)k * NE + tid + 256 * r];
        #pragma unroll
        for (int jj = 0; jj < 4; jj++) {
            float e = ejs[jj][k];
            #pragma unroll
            for (int r = 0; r < 4; r++) acc[jj][r] = fmaf(e, v[r], acc[jj][r]);
        }
    }

    float m1[4], m2[4];
    double s1[4], s2[4];
    #pragma unroll
    for (int jj = 0; jj < 4; jj++) { m1[jj] = 3.4e38f; m2[jj] = 3.4e38f; s1[jj] = 0.0; s2[jj] = 0.0; }

    #pragma unroll
    for (int jj = 0; jj < 4; jj++) {
        float nj = g_sume2[j0 + jj];
        #pragma unroll
        for (int r = 0; r < 4; r++) {
            int i = tid + 256 * r;
            float cdv = fmaf(-2.f, acc[jj][r], __fadd_rn(nj, g_sume2[i]));
            if (cdv < m1[jj]) { m2[jj] = m1[jj]; m1[jj] = cdv; }
            else if (cdv < m2[jj]) m2[jj] = cdv;
            s1[jj] += (double)cdv;
            s2[jj] += (double)cdv * (double)cdv;
        }
    }

    for (int jj = 0; jj < 4; jj++) {
        sm1[tid] = m1[jj]; sm2[tid] = m2[jj]; ss1[tid] = s1[jj]; ss2[tid] = s2[jj];
        __syncthreads();
        for (int o = 128; o; o >>= 1) {
            if (tid < o) {
                float a1 = sm1[tid], a2 = sm2[tid];
                float b1 = sm1[tid + o], b2 = sm2[tid + o];
                float n1 = fminf(a1, b1);
                float n2 = fminf(fmaxf(a1, b1), fminf(a2, b2));
                sm1[tid] = n1; sm2[tid] = n2;
                ss1[tid] += ss1[tid + o];
                ss2[tid] += ss2[tid + o];
            }
            __syncthreads();
        }
        if (tid == 0) {
            g_md[j0 + jj] = sm2[0];   // second smallest (diag ~0 is the smallest)
            double var = (ss2[0] - ss1[0] * ss1[0] / 1024.0) / 1023.0;
            g_var[j0 + jj] = (float)var;
        }
        __syncthreads();
    }
}

// ---------------- K5: final scalars ----------------
__global__ void k_final(float* __restrict__ out) {
    __shared__ double red[256];
    int tid = threadIdx.x;

    // loss
    red[tid] = (double)g_loss_part[tid];
    __syncthreads();
    #pragma unroll
    for (int o = 128; o; o >>= 1) {
        if (tid < o) red[tid] += red[tid + o];
        __syncthreads();
    }
    if (tid == 0) {
        float m = (float)(red[0] / (double)((size_t)TOK * CDIM));
        out[LOSS_OFF] = __fadd_rn(__fmul_rn(0.2f, m), m);   // beta*mse + mse
    }
    __syncthreads();

    // mean codebook distance + variance
    double a = 0.0, v = 0.0;
    for (int i = tid; i < NE; i += 256) { a += (double)g_md[i]; v += (double)g_var[i]; }
    red[tid] = a; __syncthreads();
    #pragma unroll
    for (int o = 128; o; o >>= 1) { if (tid < o) red[tid] += red[tid + o]; __syncthreads(); }
    if (tid == 0) out[MCD_OFF] = (float)(red[0] / 1024.0);
    __syncthreads();
    red[tid] = v; __syncthreads();
    #pragma unroll
    for (int o = 128; o; o >>= 1) { if (tid < o) red[tid] += red[tid + o]; __syncthreads(); }
    if (tid == 0) out[MCV_OFF] = (float)(red[0] / 1024.0);
}

// ---------------- launch ----------------
extern "C" void kernel_launch(void* const* d_in, const int* in_sizes, int n_in,
                              void* d_out, int out_size) {
    const float* z   = (const float*)d_in[0];
    const float* emb = (const float*)d_in[1];
    float* out = (float*)d_out;

    k_sume2 <<<128, dim3(32, 8)>>>(emb);
    k_embT  <<<dim3(32, 8), dim3(32, 8)>>>(emb);
    k_dist  <<<1024, 128>>>(z);
    k_init  <<<8, 256>>>(out);
    k_gather<<<256, 256>>>(z, emb, out);
    k_cbstats<<<256, 256>>>(emb);
    k_final <<<1, 256>>>(out);
}